// round 6
// baseline (speedup 1.0000x reference)
#include <cuda_runtime.h>
#include <math.h>

// ---------------------------------------------------------------------------
// casConv2d: B=1, C=128, H=W=32, OC=128, K=3, pad=1 -> OH=OW=32, L=1024
// 36 real chunks of 32 ckk-terms; front-pad chunk is exactly zero after quant.
//
// INSTRUMENTATION ROUND: launches = p q p p p (extra p's are idempotent) so
// the ncu window (positions 3-5, calibrated in R5) profiles k_partials.
//
// K1 change: w_s -> [32][128] with XOR swizzle (oc ^ ((m&15)<<1)):
//   STS conflicts 16-way -> 2-way; LDS read side stays 2-addr broadcast.
// ---------------------------------------------------------------------------

typedef unsigned long long u64;

__device__ float g_part[1024u * 36u * 128u];  // [l][j][oc]

__device__ __forceinline__ u64 fma2(u64 a, u64 b, u64 c) {
    u64 d;
    asm("fma.rn.f32x2 %0, %1, %2, %3;" : "=l"(d) : "l"(a), "l"(b), "l"(c));
    return d;
}

__device__ __forceinline__ u64 bcast2(float v) {
    u64 d;
    unsigned u = __float_as_uint(v);
    asm("mov.b64 %0, {%1, %1};" : "=l"(d) : "r"(u));
    return d;
}

__device__ __forceinline__ float2 unpack2(u64 v) {
    float2 f;
    asm("mov.b64 {%0, %1}, %2;" : "=f"(f.x), "=f"(f.y) : "l"(v));
    return f;
}

// ---------------------------------------------------------------------------
// Kernel 1: chunk partial sums. grid = (16 l-tiles, 36 chunks), block = 256.
// Block tile: 128 oc x 64 l (2 rows x 32 cols); thread tile 8 oc x 4 l.
// ---------------------------------------------------------------------------
__global__ void __launch_bounds__(256)
k_partials(const float* __restrict__ x, const float* __restrict__ w) {
    __shared__ float x_s[5 * 4 * 34];     // [c_rel][row(4)][col(34)], zero halo
    __shared__ float w_s[32 * 128];       // [m][oc^((m&15)<<1)]  (swizzled)
    __shared__ int   xoff_s[32];

    const int j    = blockIdx.y;
    const int oh0  = blockIdx.x * 2;
    const int base = 32 * j;
    const int cmin = base / 9;
    const int r0   = base - 9 * cmin;
    const int tid  = threadIdx.x;

    if (tid < 32) {
        int idx9 = r0 + tid;
        int cr   = idx9 / 9;
        int rem  = idx9 - cr * 9;
        int kh   = rem / 3;
        int kw   = rem - kh * 3;
        xoff_s[tid] = cr * 136 + kh * 34 + kw;
    }

    for (int e = tid; e < 5 * 4 * 34; e += 256) {
        int cr  = e / 136;
        int rem = e - cr * 136;
        int rr  = rem / 34;
        int cc  = rem - rr * 34;
        int c   = cmin + cr;
        int gh  = oh0 - 1 + rr;
        int gw  = cc - 1;
        float v = 0.0f;
        if (c < 128 && (unsigned)gh < 32u && (unsigned)gw < 32u)
            v = x[(c << 10) + (gh << 5) + gw];
        x_s[e] = v;
    }
    // w load: coalesced LDG, 2-way-conflict swizzled STS
    for (int e = tid; e < 4096; e += 256) {
        int oc = e >> 5;
        int m  = e & 31;
        w_s[(m << 7) + (oc ^ ((m & 15) << 1))] = w[oc * 1152 + base + m];
    }
    __syncthreads();

    const int lcol = tid & 15;
    const int oc0  = (tid >> 4) << 3;
    const int lrow = lcol >> 3;
    const int colb = (lcol & 7) << 2;
    const int xrowoff = lrow * 34 + colb;

    u64 acc[4][4];
#pragma unroll
    for (int p = 0; p < 4; ++p)
#pragma unroll
        for (int i = 0; i < 4; ++i) acc[p][i] = 0ull;

#pragma unroll
    for (int t = 0; t < 32; ++t) {
        const int xh = ((t >> 2) & 3) << 3;     // compile-time per t
        const int xl = (t & 3) << 1;
        const float* xr = &x_s[xoff_s[t] + xrowoff];
        const u64*   wr = (const u64*)&w_s[(t << 7) + (oc0 ^ xh)];
        const u64 w0 = wr[(0 ^ xl) >> 1];
        const u64 w1 = wr[(2 ^ xl) >> 1];
        const u64 w2 = wr[(4 ^ xl) >> 1];
        const u64 w3 = wr[(6 ^ xl) >> 1];
#pragma unroll
        for (int i = 0; i < 4; ++i) {
            const u64 xx = bcast2(xr[i]);
            acc[0][i] = fma2(w0, xx, acc[0][i]);
            acc[1][i] = fma2(w1, xx, acc[1][i]);
            acc[2][i] = fma2(w2, xx, acc[2][i]);
            acc[3][i] = fma2(w3, xx, acc[3][i]);
        }
    }

    const int lbase = (oh0 + lrow) * 32 + colb;
    float* outp = g_part + (size_t)(j << 7) + oc0;
#pragma unroll
    for (int i = 0; i < 4; ++i) {
        float2 a0 = unpack2(acc[0][i]);
        float2 a1 = unpack2(acc[1][i]);
        float2 a2 = unpack2(acc[2][i]);
        float2 a3 = unpack2(acc[3][i]);
        float* po = outp + (size_t)(lbase + i) * 4608;
        *(float4*)(po)     = make_float4(a0.x, a0.y, a1.x, a1.y);
        *(float4*)(po + 4) = make_float4(a2.x, a2.y, a3.x, a3.y);
    }
}

// ---------------------------------------------------------------------------
// Kernel 2: block (128 thr, 4 warps) per l; grid = 1024.  (unchanged R5)
// ---------------------------------------------------------------------------
__global__ void __launch_bounds__(128)
k_quant(const float* __restrict__ bias, float* __restrict__ out) {
    const int tid  = threadIdx.x;
    const int lane = tid & 31;
    const int wid  = tid >> 5;
    const int l    = blockIdx.x;
    const int j0   = wid * 9;

    const float4* bp = (const float4*)(g_part + (size_t)l * 4608) + lane;

    __shared__ float4 s[4][32];

    float4 t4 = make_float4(0.f, 0.f, 0.f, 0.f);
#pragma unroll
    for (int j = 0; j < 9; ++j) {
        float4 v = bp[(j0 + j) * 32];
        t4.x += v.x; t4.y += v.y; t4.z += v.z; t4.w += v.w;
    }
    s[wid][lane] = t4;
    __syncthreads();

    float4 tot = *(const float4*)(bias + (lane << 2));
#pragma unroll
    for (int w2 = 0; w2 < 4; ++w2) {
        float4 v = s[w2][lane];
        tot.x += v.x; tot.y += v.y; tot.z += v.z; tot.w += v.w;
    }
    float mx = fmaxf(fmaxf(tot.x, tot.y), fmaxf(tot.z, tot.w));
    float mn = fminf(fminf(tot.x, tot.y), fminf(tot.z, tot.w));
#pragma unroll
    for (int sft = 16; sft > 0; sft >>= 1) {
        mx = fmaxf(mx, __shfl_xor_sync(0xffffffffu, mx, sft));
        mn = fminf(mn, __shfl_xor_sync(0xffffffffu, mn, sft));
    }

    const float sc = (mx - mn) * (1.0f / 255.0f);
    float z = -mn / sc;
    z = fminf(fmaxf(z, 0.0f), 255.0f);
    if (isnan(z)) z = 0.0f;
    const float zp  = truncf(z);
    const float rcp = 1.0f / sc;

    float4 o = make_float4(0.f, 0.f, 0.f, 0.f);
#pragma unroll
    for (int j = 0; j < 9; ++j) {
        float4 v = bp[(j0 + j) * 32];
        o.x += fminf(fmaxf(rintf(v.x * rcp) + zp, 0.0f), 255.0f) - zp;
        o.y += fminf(fmaxf(rintf(v.y * rcp) + zp, 0.0f), 255.0f) - zp;
        o.z += fminf(fmaxf(rintf(v.z * rcp) + zp, 0.0f), 255.0f) - zp;
        o.w += fminf(fmaxf(rintf(v.w * rcp) + zp, 0.0f), 255.0f) - zp;
    }
    __syncthreads();
    s[wid][lane] = o;
    __syncthreads();

    const float* sf = (const float*)s;
    float v = sf[tid] + sf[128 + tid] + sf[256 + tid] + sf[384 + tid];
    out[(tid << 10) + l] = v * sc;
}

// ---------------------------------------------------------------------------
extern "C" void kernel_launch(void* const* d_in, const int* in_sizes, int n_in,
                              void* d_out, int out_size) {
    const float *x = nullptr, *w = nullptr, *b = nullptr;
    for (int i = 0; i < n_in; ++i) {
        if      (in_sizes[i] == 131072) x = (const float*)d_in[i];  // 128*32*32
        else if (in_sizes[i] == 147456) w = (const float*)d_in[i];  // 128*128*9
        else if (in_sizes[i] == 128)    b = (const float*)d_in[i];
    }
    k_partials<<<dim3(16, 36), 256>>>(x, w);
    k_quant<<<1024, 128>>>(b, (float*)d_out);
    // Idempotent replays occupying the ncu window (positions 3-5):
    k_partials<<<dim3(16, 36), 256>>>(x, w);
    k_partials<<<dim3(16, 36), 256>>>(x, w);
    k_partials<<<dim3(16, 36), 256>>>(x, w);
}

// round 7
// speedup vs baseline: 2.2482x; 2.2482x over previous
#include <cuda_runtime.h>
#include <math.h>

// ---------------------------------------------------------------------------
// casConv2d: B=1, C=128, H=W=32, OC=128, K=3, pad=1 -> OH=OW=32, L=1024
// 36 real chunks of 32 ckk-terms; front-pad chunk is exactly zero after quant.
//
// Kernel 1: per-chunk partial sums -> g_part[l][j][oc]
//   grid (32 rows, 36 chunks), block 256 = 32 oc-quads x 8 l-quads.
//   Inner loop fully compile-time via template<R0> (R0 = base%9, 9 variants):
//   all smem offsets constant -> ptxas hoists/CSEs x loads, schedules deep.
//   x stored duplicated (v,v) as u64 so fma.rn.f32x2 reads it directly.
// Kernel 2: block-per-l reduce/quant (unchanged).
// ---------------------------------------------------------------------------

typedef unsigned long long u64;

__device__ float g_part[1024u * 36u * 128u];  // [l][j][oc]

__device__ __forceinline__ u64 fma2(u64 a, u64 b, u64 c) {
    u64 d;
    asm("fma.rn.f32x2 %0, %1, %2, %3;" : "=l"(d) : "l"(a), "l"(b), "l"(c));
    return d;
}

__device__ __forceinline__ float2 unpack2(u64 v) {
    float2 f;
    asm("mov.b64 {%0, %1}, %2;" : "=f"(f.x), "=f"(f.y) : "l"(v));
    return f;
}

// Compile-time chunk body: R0 = base % 9. idx9 = R0+t -> (cr, kh, kw) const.
// w_s swizzle: float slot = (m<<7) + (oc ^ ((m&15)<<1)); for a 4-aligned quad
// oc0 this is u64 base ((oc0 ^ ((t&14)<<1))>>1) with halves swapped when t&1.
template<int R0>
__device__ __forceinline__ void do_chunk(const u64* xs, const float* ws,
                                         int colb, int oc0, u64 (&acc)[2][4]) {
#pragma unroll
    for (int t = 0; t < 32; ++t) {
        const int idx9  = R0 + t;
        const int cr    = idx9 / 9;
        const int rem   = idx9 - cr * 9;
        const int kh    = rem / 3;
        const int kw    = rem - kh * 3;
        const int xorhi = (t & 14) << 1;   // multiple of 4
        const int sel   = t & 1;
        const u64* xr = xs + (cr * 3 + kh) * 34 + colb + kw;
        const u64* wq = (const u64*)(ws + (t << 7)) + ((oc0 ^ xorhi) >> 1);
        const u64 wlo = wq[sel];           // (w[oc0],   w[oc0+1])
        const u64 whi = wq[1 - sel];       // (w[oc0+2], w[oc0+3])
#pragma unroll
        for (int i = 0; i < 4; ++i) {
            const u64 xx = xr[i];          // duplicated (x, x)
            acc[0][i] = fma2(wlo, xx, acc[0][i]);
            acc[1][i] = fma2(whi, xx, acc[1][i]);
        }
    }
}

__global__ void __launch_bounds__(256)
k_partials(const float* __restrict__ x, const float* __restrict__ w) {
    __shared__ u64   x_s[5 * 3 * 34];     // [c_rel][kh(3)][col(34)], (v,v) dup
    __shared__ float w_s[32 * 128];       // [m][oc ^ ((m&15)<<1)]

    const int j    = blockIdx.y;
    const int oh   = blockIdx.x;
    const int base = 32 * j;
    const int cmin = base / 9;
    const int r0   = base - 9 * cmin;
    const int tid  = threadIdx.x;

    // x halo: 5 channels x 3 rows x 34 cols, zero-padded, duplicated to u64
    for (int e = tid; e < 510; e += 256) {
        int cr  = e / 102;
        int rem = e - cr * 102;
        int kh  = rem / 34;
        int col = rem - kh * 34;
        int c   = cmin + cr;
        int gh  = oh - 1 + kh;
        int gw  = col - 1;
        float v = 0.0f;
        if (c < 128 && (unsigned)gh < 32u && (unsigned)gw < 32u)
            v = x[(c << 10) + (gh << 5) + gw];
        unsigned uv = __float_as_uint(v);
        x_s[e] = ((u64)uv << 32) | uv;
    }
    // w chunk: coalesced LDG, 2-way-conflict swizzled STS
    for (int e = tid; e < 4096; e += 256) {
        int oc = e >> 5;
        int m  = e & 31;
        w_s[(m << 7) + (oc ^ ((m & 15) << 1))] = w[oc * 1152 + base + m];
    }
    __syncthreads();

    const int oc0  = (tid >> 3) << 2;     // 32 oc-quads
    const int colb = (tid & 7) << 2;      // 8 l-quads (ow)

    u64 acc[2][4] = {};
    switch (r0) {
        case 0: do_chunk<0>(x_s, w_s, colb, oc0, acc); break;
        case 1: do_chunk<1>(x_s, w_s, colb, oc0, acc); break;
        case 2: do_chunk<2>(x_s, w_s, colb, oc0, acc); break;
        case 3: do_chunk<3>(x_s, w_s, colb, oc0, acc); break;
        case 4: do_chunk<4>(x_s, w_s, colb, oc0, acc); break;
        case 5: do_chunk<5>(x_s, w_s, colb, oc0, acc); break;
        case 6: do_chunk<6>(x_s, w_s, colb, oc0, acc); break;
        case 7: do_chunk<7>(x_s, w_s, colb, oc0, acc); break;
        default: do_chunk<8>(x_s, w_s, colb, oc0, acc); break;
    }

    // store: g_part[l][j][oc], l = oh*32 + colb + i
    float* po = g_part + ((size_t)(oh << 5) + colb) * 4608 + (j << 7) + oc0;
#pragma unroll
    for (int i = 0; i < 4; ++i) {
        float2 a0 = unpack2(acc[0][i]);
        float2 a1 = unpack2(acc[1][i]);
        *(float4*)(po + (size_t)i * 4608) = make_float4(a0.x, a0.y, a1.x, a1.y);
    }
}

// ---------------------------------------------------------------------------
// Kernel 2: block (128 thr, 4 warps) per l; grid = 1024.  (unchanged)
// ---------------------------------------------------------------------------
__global__ void __launch_bounds__(128)
k_quant(const float* __restrict__ bias, float* __restrict__ out) {
    const int tid  = threadIdx.x;
    const int lane = tid & 31;
    const int wid  = tid >> 5;
    const int l    = blockIdx.x;
    const int j0   = wid * 9;

    const float4* bp = (const float4*)(g_part + (size_t)l * 4608) + lane;

    __shared__ float4 s[4][32];

    float4 t4 = make_float4(0.f, 0.f, 0.f, 0.f);
#pragma unroll
    for (int j = 0; j < 9; ++j) {
        float4 v = bp[(j0 + j) * 32];
        t4.x += v.x; t4.y += v.y; t4.z += v.z; t4.w += v.w;
    }
    s[wid][lane] = t4;
    __syncthreads();

    float4 tot = *(const float4*)(bias + (lane << 2));
#pragma unroll
    for (int w2 = 0; w2 < 4; ++w2) {
        float4 v = s[w2][lane];
        tot.x += v.x; tot.y += v.y; tot.z += v.z; tot.w += v.w;
    }
    float mx = fmaxf(fmaxf(tot.x, tot.y), fmaxf(tot.z, tot.w));
    float mn = fminf(fminf(tot.x, tot.y), fminf(tot.z, tot.w));
#pragma unroll
    for (int sft = 16; sft > 0; sft >>= 1) {
        mx = fmaxf(mx, __shfl_xor_sync(0xffffffffu, mx, sft));
        mn = fminf(mn, __shfl_xor_sync(0xffffffffu, mn, sft));
    }

    const float sc = (mx - mn) * (1.0f / 255.0f);
    float z = -mn / sc;
    z = fminf(fmaxf(z, 0.0f), 255.0f);
    if (isnan(z)) z = 0.0f;
    const float zp  = truncf(z);
    const float rcp = 1.0f / sc;

    float4 o = make_float4(0.f, 0.f, 0.f, 0.f);
#pragma unroll
    for (int j = 0; j < 9; ++j) {
        float4 v = bp[(j0 + j) * 32];
        o.x += fminf(fmaxf(rintf(v.x * rcp) + zp, 0.0f), 255.0f) - zp;
        o.y += fminf(fmaxf(rintf(v.y * rcp) + zp, 0.0f), 255.0f) - zp;
        o.z += fminf(fmaxf(rintf(v.z * rcp) + zp, 0.0f), 255.0f) - zp;
        o.w += fminf(fmaxf(rintf(v.w * rcp) + zp, 0.0f), 255.0f) - zp;
    }
    __syncthreads();
    s[wid][lane] = o;
    __syncthreads();

    const float* sf = (const float*)s;
    float v = sf[tid] + sf[128 + tid] + sf[256 + tid] + sf[384 + tid];
    out[(tid << 10) + l] = v * sc;
}

// ---------------------------------------------------------------------------
extern "C" void kernel_launch(void* const* d_in, const int* in_sizes, int n_in,
                              void* d_out, int out_size) {
    const float *x = nullptr, *w = nullptr, *b = nullptr;
    for (int i = 0; i < n_in; ++i) {
        if      (in_sizes[i] == 131072) x = (const float*)d_in[i];  // 128*32*32
        else if (in_sizes[i] == 147456) w = (const float*)d_in[i];  // 128*128*9
        else if (in_sizes[i] == 128)    b = (const float*)d_in[i];
    }
    k_partials<<<dim3(32, 36), 256>>>(x, w);
    k_quant<<<1024, 128>>>(b, (float*)d_out);
}

// round 8
// speedup vs baseline: 2.9227x; 1.3000x over previous
#include <cuda_runtime.h>
#include <math.h>

// ---------------------------------------------------------------------------
// casConv2d: B=1, C=128, H=W=32, OC=128, K=3, pad=1 -> OH=OW=32, L=1024
// 36 real chunks of 32 ckk-terms; front-pad chunk is exactly zero after quant.
//
// Kernel 1 (R6 version, known 15.4us): per-chunk partial sums
//   -> g_part[l][j][oc], grid (16 l-tiles, 36 chunks), block 256.
// Kernel 2: block-per-l reduce/quant, chunks held in REGISTERS between the
//   totals pass and the quant pass (single 18.9MB L2 read instead of two).
// ---------------------------------------------------------------------------

typedef unsigned long long u64;

__device__ float g_part[1024u * 36u * 128u];  // [l][j][oc]

__device__ __forceinline__ u64 fma2(u64 a, u64 b, u64 c) {
    u64 d;
    asm("fma.rn.f32x2 %0, %1, %2, %3;" : "=l"(d) : "l"(a), "l"(b), "l"(c));
    return d;
}

__device__ __forceinline__ u64 bcast2(float v) {
    u64 d;
    unsigned u = __float_as_uint(v);
    asm("mov.b64 %0, {%1, %1};" : "=l"(d) : "r"(u));
    return d;
}

__device__ __forceinline__ float2 unpack2(u64 v) {
    float2 f;
    asm("mov.b64 {%0, %1}, %2;" : "=f"(f.x), "=f"(f.y) : "l"(v));
    return f;
}

// ---------------------------------------------------------------------------
// Kernel 1: chunk partial sums. grid = (16 l-tiles, 36 chunks), block = 256.
// Block tile: 128 oc x 64 l (2 rows x 32 cols); thread tile 8 oc x 4 l.
// ---------------------------------------------------------------------------
__global__ void __launch_bounds__(256)
k_partials(const float* __restrict__ x, const float* __restrict__ w) {
    __shared__ float x_s[5 * 4 * 34];     // [c_rel][row(4)][col(34)], zero halo
    __shared__ float w_s[32 * 128];       // [m][oc^((m&15)<<1)]  (swizzled)
    __shared__ int   xoff_s[32];

    const int j    = blockIdx.y;
    const int oh0  = blockIdx.x * 2;
    const int base = 32 * j;
    const int cmin = base / 9;
    const int r0   = base - 9 * cmin;
    const int tid  = threadIdx.x;

    if (tid < 32) {
        int idx9 = r0 + tid;
        int cr   = idx9 / 9;
        int rem  = idx9 - cr * 9;
        int kh   = rem / 3;
        int kw   = rem - kh * 3;
        xoff_s[tid] = cr * 136 + kh * 34 + kw;
    }

    for (int e = tid; e < 5 * 4 * 34; e += 256) {
        int cr  = e / 136;
        int rem = e - cr * 136;
        int rr  = rem / 34;
        int cc  = rem - rr * 34;
        int c   = cmin + cr;
        int gh  = oh0 - 1 + rr;
        int gw  = cc - 1;
        float v = 0.0f;
        if (c < 128 && (unsigned)gh < 32u && (unsigned)gw < 32u)
            v = x[(c << 10) + (gh << 5) + gw];
        x_s[e] = v;
    }
    for (int e = tid; e < 4096; e += 256) {
        int oc = e >> 5;
        int m  = e & 31;
        w_s[(m << 7) + (oc ^ ((m & 15) << 1))] = w[oc * 1152 + base + m];
    }
    __syncthreads();

    const int lcol = tid & 15;
    const int oc0  = (tid >> 4) << 3;
    const int lrow = lcol >> 3;
    const int colb = (lcol & 7) << 2;
    const int xrowoff = lrow * 34 + colb;

    u64 acc[4][4];
#pragma unroll
    for (int p = 0; p < 4; ++p)
#pragma unroll
        for (int i = 0; i < 4; ++i) acc[p][i] = 0ull;

#pragma unroll
    for (int t = 0; t < 32; ++t) {
        const int xh = ((t >> 2) & 3) << 3;
        const int xl = (t & 3) << 1;
        const float* xr = &x_s[xoff_s[t] + xrowoff];
        const u64*   wr = (const u64*)&w_s[(t << 7) + (oc0 ^ xh)];
        const u64 w0 = wr[(0 ^ xl) >> 1];
        const u64 w1 = wr[(2 ^ xl) >> 1];
        const u64 w2 = wr[(4 ^ xl) >> 1];
        const u64 w3 = wr[(6 ^ xl) >> 1];
#pragma unroll
        for (int i = 0; i < 4; ++i) {
            const u64 xx = bcast2(xr[i]);
            acc[0][i] = fma2(w0, xx, acc[0][i]);
            acc[1][i] = fma2(w1, xx, acc[1][i]);
            acc[2][i] = fma2(w2, xx, acc[2][i]);
            acc[3][i] = fma2(w3, xx, acc[3][i]);
        }
    }

    const int lbase = (oh0 + lrow) * 32 + colb;
    float* outp = g_part + (size_t)(j << 7) + oc0;
#pragma unroll
    for (int i = 0; i < 4; ++i) {
        float2 a0 = unpack2(acc[0][i]);
        float2 a1 = unpack2(acc[1][i]);
        float2 a2 = unpack2(acc[2][i]);
        float2 a3 = unpack2(acc[3][i]);
        float* po = outp + (size_t)(lbase + i) * 4608;
        *(float4*)(po)     = make_float4(a0.x, a0.y, a1.x, a1.y);
        *(float4*)(po + 4) = make_float4(a2.x, a2.y, a3.x, a3.y);
    }
}

// ---------------------------------------------------------------------------
// Kernel 2: block (128 thr, 4 warps) per l; grid = 1024.
// Warp w handles chunks j in [9w, 9w+9); lane holds oc quad lane*4..+3.
// Chunks cached in registers: single global read of g_part.
// ---------------------------------------------------------------------------
__global__ void __launch_bounds__(128)
k_quant(const float* __restrict__ bias, float* __restrict__ out) {
    const int tid  = threadIdx.x;
    const int lane = tid & 31;
    const int wid  = tid >> 5;
    const int l    = blockIdx.x;
    const int j0   = wid * 9;

    const float4* bp = (const float4*)(g_part + (size_t)l * 4608) + lane;

    __shared__ float4 s[4][32];

    // --- single load: 9 chunks into registers; per-warp totals
    float4 vj[9];
    float4 t4 = make_float4(0.f, 0.f, 0.f, 0.f);
#pragma unroll
    for (int j = 0; j < 9; ++j) {
        vj[j] = bp[(j0 + j) * 32];
        t4.x += vj[j].x; t4.y += vj[j].y; t4.z += vj[j].z; t4.w += vj[j].w;
    }
    s[wid][lane] = t4;
    __syncthreads();

    // full totals (+bias), redundantly in every warp
    float4 tot = *(const float4*)(bias + (lane << 2));
#pragma unroll
    for (int w2 = 0; w2 < 4; ++w2) {
        float4 v = s[w2][lane];
        tot.x += v.x; tot.y += v.y; tot.z += v.z; tot.w += v.w;
    }
    float mx = fmaxf(fmaxf(tot.x, tot.y), fmaxf(tot.z, tot.w));
    float mn = fminf(fminf(tot.x, tot.y), fminf(tot.z, tot.w));
#pragma unroll
    for (int sft = 16; sft > 0; sft >>= 1) {
        mx = fmaxf(mx, __shfl_xor_sync(0xffffffffu, mx, sft));
        mn = fminf(mn, __shfl_xor_sync(0xffffffffu, mn, sft));
    }

    const float sc = (mx - mn) * (1.0f / 255.0f);
    float z = -mn / sc;                              // inf/nan if sc==0
    z = fminf(fmaxf(z, 0.0f), 255.0f);               // clip (nan -> 0 via fmaxf)
    if (isnan(z)) z = 0.0f;
    const float zp  = truncf(z);                     // .int() truncation
    const float rcp = 1.0f / sc;

    // --- quant from registers (no reload), sum (q - zp) exactly
    float4 o = make_float4(0.f, 0.f, 0.f, 0.f);
#pragma unroll
    for (int j = 0; j < 9; ++j) {
        o.x += fminf(fmaxf(rintf(vj[j].x * rcp) + zp, 0.0f), 255.0f) - zp;
        o.y += fminf(fmaxf(rintf(vj[j].y * rcp) + zp, 0.0f), 255.0f) - zp;
        o.z += fminf(fmaxf(rintf(vj[j].z * rcp) + zp, 0.0f), 255.0f) - zp;
        o.w += fminf(fmaxf(rintf(vj[j].w * rcp) + zp, 0.0f), 255.0f) - zp;
    }
    __syncthreads();
    s[wid][lane] = o;
    __syncthreads();

    // --- combine warps, scale, store: thread tid <-> oc = tid
    const float* sf = (const float*)s;               // [warp][oc]
    float v = sf[tid] + sf[128 + tid] + sf[256 + tid] + sf[384 + tid];
    out[(tid << 10) + l] = v * sc;
}

// ---------------------------------------------------------------------------
extern "C" void kernel_launch(void* const* d_in, const int* in_sizes, int n_in,
                              void* d_out, int out_size) {
    const float *x = nullptr, *w = nullptr, *b = nullptr;
    for (int i = 0; i < n_in; ++i) {
        if      (in_sizes[i] == 131072) x = (const float*)d_in[i];  // 128*32*32
        else if (in_sizes[i] == 147456) w = (const float*)d_in[i];  // 128*128*9
        else if (in_sizes[i] == 128)    b = (const float*)d_in[i];
    }
    k_partials<<<dim3(16, 36), 256>>>(x, w);
    k_quant<<<1024, 128>>>(b, (float*)d_out);
}